// round 1
// baseline (speedup 1.0000x reference)
#include <cuda_runtime.h>
#include <cstdint>

// Problem constants
#define BATCH 32
#define NEXP 8
#define CIN 64
#define COUT 64
#define HW 25600            // 160*160
#define NTILE 128           // pixels per tile
#define ITERS 4             // tiles per block
#define XS_STRIDE 136       // padded smem stride (conflict-free B-frag loads)

// Per-batch mixed weight matrices, TF32-rounded, [B][COUT][CIN]
__device__ float g_W[BATCH * COUT * CIN];

__device__ __forceinline__ uint32_t f2tf32(float f) {
    uint32_t r;
    asm("cvt.rna.tf32.f32 %0, %1;" : "=r"(r) : "f"(f));
    return r;
}

// Kernel 1: W_b[o,i] = sum_e alpha[b,e] * ke[e,o,i], rounded to tf32
__global__ void lla_weights_kernel(const float* __restrict__ alpha,
                                   const float* __restrict__ ke) {
    int b = blockIdx.x;
    __shared__ float a_s[NEXP];
    if (threadIdx.x < NEXP) a_s[threadIdx.x] = alpha[b * NEXP + threadIdx.x];
    __syncthreads();
    for (int idx = threadIdx.x; idx < COUT * CIN; idx += 256) {
        float s = 0.f;
#pragma unroll
        for (int e = 0; e < NEXP; e++)
            s = fmaf(a_s[e], ke[e * COUT * CIN + idx], s);
        g_W[b * COUT * CIN + idx] = __uint_as_float(f2tf32(s));
    }
}

// Kernel 2: per-batch GEMM out[o,p] = sum_i W[o,i] * x[i,p] via tf32 mma.sync
// Block: 256 threads (8 warps). Warp w covers M-rows [16*(w&3), +16),
// N-cols [64*(w>>2), +64) within a 128-pixel tile. 4 tiles per block.
__global__ __launch_bounds__(256, 2)
void lla_conv_kernel(const float* __restrict__ x, float* __restrict__ out) {
    const int b    = blockIdx.y;
    const int tid  = threadIdx.x;
    const int lane = tid & 31;
    const int warp = tid >> 5;
    const int g    = lane >> 2;   // groupID 0..7
    const int tig  = lane & 3;    // thread-in-group 0..3
    const int m0   = (warp & 3) * 16;
    const int nh   = (warp >> 2) * 64;

    // Shared: reused region. Phase 1: W staging (64x65 floats = 4160).
    // Phase 2: X tile (64 x XS_STRIDE floats = 8704). 34816 bytes total.
    __shared__ float smem[CIN * XS_STRIDE];

    // ---- Stage W (coalesced from L2-resident g_W), build A fragments ----
    const float* Wg = g_W + b * COUT * CIN;
    for (int idx = tid; idx < COUT * CIN; idx += 256) {
        int o = idx >> 6, i = idx & 63;
        smem[o * 65 + i] = Wg[idx];
    }
    __syncthreads();

    uint32_t afr[8][4];  // 8 k-steps of m16k8 A fragments (tf32 bits)
#pragma unroll
    for (int k = 0; k < 8; k++) {
        int kc = k * 8 + tig;
        afr[k][0] = __float_as_uint(smem[(m0 + g)     * 65 + kc]);
        afr[k][1] = __float_as_uint(smem[(m0 + 8 + g) * 65 + kc]);
        afr[k][2] = __float_as_uint(smem[(m0 + g)     * 65 + kc + 4]);
        afr[k][3] = __float_as_uint(smem[(m0 + 8 + g) * 65 + kc + 4]);
    }

    const float* xb = x   + (size_t)b * CIN  * HW;
    float*       ob = out + (size_t)b * COUT * HW;

    for (int it = 0; it < ITERS; it++) {
        const int p0 = (blockIdx.x * ITERS + it) * NTILE;

        __syncthreads();  // prior smem readers done before overwrite

        // ---- Load X tile [64][128] as float4, convert to tf32 into smem ----
#pragma unroll
        for (int j = 0; j < 8; j++) {
            int idx = tid + 256 * j;          // 0..2047
            int row = idx >> 5;               // 0..63
            int q   = idx & 31;               // float4 index within row
            float4 v = *reinterpret_cast<const float4*>(xb + row * HW + p0 + q * 4);
            uint32_t* d = reinterpret_cast<uint32_t*>(&smem[row * XS_STRIDE + q * 4]);
            d[0] = f2tf32(v.x); d[1] = f2tf32(v.y);
            d[2] = f2tf32(v.z); d[3] = f2tf32(v.w);
        }
        __syncthreads();

        // ---- Compute: 8 n-tiles x 8 k-steps of m16n8k8 tf32 mma ----
        float acc[8][4];
#pragma unroll
        for (int nt = 0; nt < 8; nt++) {
            acc[nt][0] = 0.f; acc[nt][1] = 0.f; acc[nt][2] = 0.f; acc[nt][3] = 0.f;
        }
#pragma unroll
        for (int nt = 0; nt < 8; nt++) {
            const int n0 = nh + nt * 8;
#pragma unroll
            for (int k = 0; k < 8; k++) {
                uint32_t b0 = __float_as_uint(smem[(k * 8 + tig)     * XS_STRIDE + n0 + g]);
                uint32_t b1 = __float_as_uint(smem[(k * 8 + 4 + tig) * XS_STRIDE + n0 + g]);
                asm volatile(
                    "mma.sync.aligned.m16n8k8.row.col.f32.tf32.tf32.f32 "
                    "{%0,%1,%2,%3}, {%4,%5,%6,%7}, {%8,%9}, {%0,%1,%2,%3};\n"
                    : "+f"(acc[nt][0]), "+f"(acc[nt][1]),
                      "+f"(acc[nt][2]), "+f"(acc[nt][3])
                    : "r"(afr[k][0]), "r"(afr[k][1]),
                      "r"(afr[k][2]), "r"(afr[k][3]),
                      "r"(b0), "r"(b1));
            }
        }

        // ---- Store: float2 per (n-tile, row-half); sector-aligned ----
#pragma unroll
        for (int nt = 0; nt < 8; nt++) {
            const int c = nh + nt * 8 + 2 * tig;
            float2 v0 = make_float2(acc[nt][0], acc[nt][1]);
            float2 v1 = make_float2(acc[nt][2], acc[nt][3]);
            *reinterpret_cast<float2*>(ob + (size_t)(m0 + g)     * HW + p0 + c) = v0;
            *reinterpret_cast<float2*>(ob + (size_t)(m0 + 8 + g) * HW + p0 + c) = v1;
        }
    }
}

extern "C" void kernel_launch(void* const* d_in, const int* in_sizes, int n_in,
                              void* d_out, int out_size) {
    const float* x     = (const float*)d_in[0];   // [32,64,160,160]
    const float* alpha = (const float*)d_in[1];   // [32,8]
    const float* ke    = (const float*)d_in[2];   // [8,64,64,1,1]
    float*       out   = (float*)d_out;           // [32,64,160,160]

    lla_weights_kernel<<<BATCH, 256>>>(alpha, ke);

    dim3 grid(HW / (NTILE * ITERS), BATCH);       // (50, 32)
    lla_conv_kernel<<<grid, 256>>>(x, out);
}

// round 2
// speedup vs baseline: 1.1791x; 1.1791x over previous
#include <cuda_runtime.h>
#include <cstdint>

// Problem constants
#define BATCH 32
#define NEXP 8
#define CIN 64
#define COUT 64
#define HW 25600            // 160*160
#define NTILE 128           // pixels per tile
#define ITERS 4             // tiles per block
#define XS 136              // padded smem row stride in floats (conflict-free B loads)
#define BUF_FLOATS (CIN * XS)
#define SMEM_BYTES (2 * BUF_FLOATS * 4)   // 69632

// Per-batch mixed weight matrices, TF32-rounded, [B][COUT][CIN]
__device__ float g_W[BATCH * COUT * CIN];

__device__ __forceinline__ uint32_t f2tf32(float f) {
    uint32_t r;
    asm("cvt.rna.tf32.f32 %0, %1;" : "=r"(r) : "f"(f));
    return r;
}

__device__ __forceinline__ void cp_async16(float* dst_smem, const float* src_gmem) {
    uint32_t d = (uint32_t)__cvta_generic_to_shared(dst_smem);
    asm volatile("cp.async.cg.shared.global [%0], [%1], 16;\n" :: "r"(d), "l"(src_gmem));
}
__device__ __forceinline__ void cp_commit() {
    asm volatile("cp.async.commit_group;\n" ::: "memory");
}
__device__ __forceinline__ void cp_wait_all() {
    asm volatile("cp.async.wait_group 0;\n" ::: "memory");
}

// Kernel 1: W_b[o,i] = sum_e alpha[b,e] * ke[e,o,i], rounded to tf32
__global__ void lla_weights_kernel(const float* __restrict__ alpha,
                                   const float* __restrict__ ke) {
    const int b = blockIdx.x;
    __shared__ float a_s[NEXP];
    if (threadIdx.x < NEXP) a_s[threadIdx.x] = alpha[b * NEXP + threadIdx.x];
    __syncthreads();
    const int idx = blockIdx.y * 1024 + threadIdx.x;  // 4 chunks of 1024
#pragma unroll 4
    for (int i = idx; i < (blockIdx.y + 1) * 1024; i += 256) {
        float s = 0.f;
#pragma unroll
        for (int e = 0; e < NEXP; e++)
            s = fmaf(a_s[e], ke[e * COUT * CIN + i], s);
        g_W[b * COUT * CIN + i] = __uint_as_float(f2tf32(s));
    }
}

// Kernel 2: per-batch GEMM out[o,p] = sum_i W[o,i] * x[i,p] via tf32 mma.sync,
// cp.async double-buffered over 4 x 128-pixel tiles.
__global__ __launch_bounds__(256, 2)
void lla_conv_kernel(const float* __restrict__ x, float* __restrict__ out) {
    extern __shared__ float smem[];
    float* const buf0 = smem;
    float* const buf1 = smem + BUF_FLOATS;

    const int b    = blockIdx.y;
    const int tid  = threadIdx.x;
    const int lane = tid & 31;
    const int warp = tid >> 5;
    const int g    = lane >> 2;   // groupID 0..7
    const int tig  = lane & 3;    // thread-in-group 0..3
    const int m0   = (warp & 3) * 16;
    const int nh   = (warp >> 2) * 64;

    const float* xb = x   + (size_t)b * CIN  * HW;
    float*       ob = out + (size_t)b * COUT * HW;
    const int pbase = blockIdx.x * (NTILE * ITERS);

    // ---- Prefetch tile 0 into buf0 (overlaps with W staging below) ----
#pragma unroll
    for (int j = 0; j < 8; j++) {
        int idx = tid + 256 * j;          // 0..2047
        int row = idx >> 5;
        int q   = idx & 31;
        cp_async16(buf0 + row * XS + q * 4, xb + row * HW + pbase + q * 4);
    }
    cp_commit();

    // ---- Stage W into buf1 region, build A fragments (tf32 already) ----
    const float* Wg = g_W + b * COUT * CIN;
    for (int idx = tid; idx < COUT * CIN; idx += 256) {
        int o = idx >> 6, i = idx & 63;
        buf1[o * 65 + i] = Wg[idx];
    }
    __syncthreads();

    uint32_t afr[8][4];  // 8 k-steps of m16k8 A fragments
#pragma unroll
    for (int k = 0; k < 8; k++) {
        int kc = k * 8 + tig;
        afr[k][0] = __float_as_uint(buf1[(m0 + g)     * 65 + kc]);
        afr[k][1] = __float_as_uint(buf1[(m0 + 8 + g) * 65 + kc]);
        afr[k][2] = __float_as_uint(buf1[(m0 + g)     * 65 + kc + 4]);
        afr[k][3] = __float_as_uint(buf1[(m0 + 8 + g) * 65 + kc + 4]);
    }
    __syncthreads();  // all afr reads done before buf1 may be overwritten

    for (int it = 0; it < ITERS; it++) {
        float* const cur = (it & 1) ? buf1 : buf0;
        float* const nxt = (it & 1) ? buf0 : buf1;
        const int p0 = pbase + it * NTILE;

        cp_wait_all();       // current tile data landed
        __syncthreads();     // ...and everyone finished reading 'nxt' last iter

        // ---- Prefetch next tile (overlaps with compute of current) ----
        if (it + 1 < ITERS) {
            const int pn = p0 + NTILE;
#pragma unroll
            for (int j = 0; j < 8; j++) {
                int idx = tid + 256 * j;
                int row = idx >> 5;
                int q   = idx & 31;
                cp_async16(nxt + row * XS + q * 4, xb + row * HW + pn + q * 4);
            }
            cp_commit();
        }

        // ---- Compute: 8 n-tiles x 8 k-steps of m16n8k8 tf32 mma ----
        float acc[8][4];
#pragma unroll
        for (int nt = 0; nt < 8; nt++) {
            acc[nt][0] = 0.f; acc[nt][1] = 0.f; acc[nt][2] = 0.f; acc[nt][3] = 0.f;
        }
#pragma unroll
        for (int nt = 0; nt < 8; nt++) {
            const int n0 = nh + nt * 8;
#pragma unroll
            for (int k = 0; k < 8; k++) {
                uint32_t b0 = f2tf32(cur[(k * 8 + tig)     * XS + n0 + g]);
                uint32_t b1 = f2tf32(cur[(k * 8 + 4 + tig) * XS + n0 + g]);
                asm volatile(
                    "mma.sync.aligned.m16n8k8.row.col.f32.tf32.tf32.f32 "
                    "{%0,%1,%2,%3}, {%4,%5,%6,%7}, {%8,%9}, {%0,%1,%2,%3};\n"
                    : "+f"(acc[nt][0]), "+f"(acc[nt][1]),
                      "+f"(acc[nt][2]), "+f"(acc[nt][3])
                    : "r"(afr[k][0]), "r"(afr[k][1]),
                      "r"(afr[k][2]), "r"(afr[k][3]),
                      "r"(b0), "r"(b1));
            }
        }

        // ---- Streaming stores: float2 per (n-tile, row-half) ----
#pragma unroll
        for (int nt = 0; nt < 8; nt++) {
            const int c = nh + nt * 8 + 2 * tig;
            float2 v0 = make_float2(acc[nt][0], acc[nt][1]);
            float2 v1 = make_float2(acc[nt][2], acc[nt][3]);
            __stcs(reinterpret_cast<float2*>(ob + (size_t)(m0 + g)     * HW + p0 + c), v0);
            __stcs(reinterpret_cast<float2*>(ob + (size_t)(m0 + 8 + g) * HW + p0 + c), v1);
        }
    }
}

extern "C" void kernel_launch(void* const* d_in, const int* in_sizes, int n_in,
                              void* d_out, int out_size) {
    const float* x     = (const float*)d_in[0];   // [32,64,160,160]
    const float* alpha = (const float*)d_in[1];   // [32,8]
    const float* ke    = (const float*)d_in[2];   // [8,64,64,1,1]
    float*       out   = (float*)d_out;           // [32,64,160,160]

    cudaFuncSetAttribute(lla_conv_kernel,
                         cudaFuncAttributeMaxDynamicSharedMemorySize, SMEM_BYTES);

    dim3 wgrid(BATCH, 4);
    lla_weights_kernel<<<wgrid, 256>>>(alpha, ke);

    dim3 grid(HW / (NTILE * ITERS), BATCH);       // (50, 32)
    lla_conv_kernel<<<grid, 256, SMEM_BYTES>>>(x, out);
}

// round 3
// speedup vs baseline: 1.1999x; 1.0176x over previous
#include <cuda_runtime.h>
#include <cstdint>

// Problem constants
#define BATCH 32
#define NEXP 8
#define CIN 64
#define COUT 64
#define HW 25600            // 160*160
#define NTILE 128           // pixels per tile
#define ITERS 8             // tiles per block
#define XS 136              // padded smem row stride in floats (conflict-free)
#define BUF_FLOATS (CIN * XS)
#define NBUF 3
#define SMEM_BYTES (NBUF * BUF_FLOATS * 4)   // 104448

// Per-batch mixed weight matrices, TF32-rounded, [B][COUT][CIN]
__device__ float g_W[BATCH * COUT * CIN];

__device__ __forceinline__ uint32_t f2tf32(float f) {
    uint32_t r;
    asm("cvt.rna.tf32.f32 %0, %1;" : "=r"(r) : "f"(f));
    return r;
}

__device__ __forceinline__ void cp_async16(float* dst_smem, const float* src_gmem) {
    uint32_t d = (uint32_t)__cvta_generic_to_shared(dst_smem);
    asm volatile("cp.async.cg.shared.global [%0], [%1], 16;\n" :: "r"(d), "l"(src_gmem));
}
__device__ __forceinline__ void cp_commit() {
    asm volatile("cp.async.commit_group;\n" ::: "memory");
}
template<int N>
__device__ __forceinline__ void cp_wait() {
    asm volatile("cp.async.wait_group %0;\n" :: "n"(N) : "memory");
}

// Kernel 1: W_b[o,i] = (1+3.38e-4) * sum_e alpha[b,e] * ke[e,o,i], tf32-RNA.
// The scale cancels the first-order bias of feeding X as truncated fp32 to
// the tf32 MMA (truncation loses mean 2^-11*ln2 relative magnitude).
__global__ void lla_weights_kernel(const float* __restrict__ alpha,
                                   const float* __restrict__ ke) {
    const int b = blockIdx.x;
    __shared__ float a_s[NEXP];
    if (threadIdx.x < NEXP) a_s[threadIdx.x] = alpha[b * NEXP + threadIdx.x];
    __syncthreads();
    const int i0 = blockIdx.y * 1024 + threadIdx.x;
#pragma unroll 4
    for (int i = i0; i < (blockIdx.y + 1) * 1024; i += 256) {
        float s = 0.f;
#pragma unroll
        for (int e = 0; e < NEXP; e++)
            s = fmaf(a_s[e], ke[e * COUT * CIN + i], s);
        g_W[b * COUT * CIN + i] = __uint_as_float(f2tf32(s * 1.000338f));
    }
}

// Kernel 2: per-batch GEMM via tf32 mma.sync, depth-2 cp.async pipeline.
__global__ __launch_bounds__(256, 2)
void lla_conv_kernel(const float* __restrict__ x, float* __restrict__ out) {
    extern __shared__ float smem[];
    float* bufs[NBUF] = { smem, smem + BUF_FLOATS, smem + 2 * BUF_FLOATS };

    const int b    = blockIdx.y;
    const int tid  = threadIdx.x;
    const int lane = tid & 31;
    const int warp = tid >> 5;
    const int g    = lane >> 2;   // 0..7
    const int tig  = lane & 3;    // 0..3
    const int m0   = (warp & 3) * 16;
    const int nh   = (warp >> 2) * 64;

    const float* xb = x   + (size_t)b * CIN  * HW;
    float*       ob = out + (size_t)b * COUT * HW;
    const int pbase = blockIdx.x * (NTILE * ITERS);

    // ---- Prefetch tiles 0,1 into buf0,buf1 ----
#pragma unroll
    for (int t = 0; t < 2; t++) {
#pragma unroll
        for (int j = 0; j < 8; j++) {
            int idx = tid + 256 * j;
            int row = idx >> 5;
            int q   = idx & 31;
            cp_async16(bufs[t] + row * XS + q * 4,
                       xb + row * HW + pbase + t * NTILE + q * 4);
        }
        cp_commit();
    }

    // ---- Stage W into buf2 region, build A fragments ----
    {
        float* wstage = bufs[2];
        const float* Wg = g_W + b * COUT * CIN;
        for (int idx = tid; idx < COUT * CIN; idx += 256) {
            int o = idx >> 6, i = idx & 63;
            wstage[o * 65 + i] = Wg[idx];
        }
    }
    __syncthreads();

    uint32_t afr[8][4];
#pragma unroll
    for (int k = 0; k < 8; k++) {
        float* wstage = bufs[2];
        int kc = k * 8 + tig;
        afr[k][0] = __float_as_uint(wstage[(m0 + g)     * 65 + kc]);
        afr[k][1] = __float_as_uint(wstage[(m0 + 8 + g) * 65 + kc]);
        afr[k][2] = __float_as_uint(wstage[(m0 + g)     * 65 + kc + 4]);
        afr[k][3] = __float_as_uint(wstage[(m0 + 8 + g) * 65 + kc + 4]);
    }

    int cb = 0;  // current buffer index
    for (int it = 0; it < ITERS; it++) {
        float* const cur = bufs[cb];
        const int p0 = pbase + it * NTILE;

        if (it < ITERS - 1) cp_wait<1>(); else cp_wait<0>();
        __syncthreads();   // tile 'it' visible to all; prior readers of the
                           // buffer we are about to refill are done

        // ---- Prefetch tile it+2 (overlaps with compute) ----
        if (it + 2 < ITERS) {
            float* const nxt = bufs[(cb + 2 >= NBUF) ? cb + 2 - NBUF : cb + 2];
            const int pn = p0 + 2 * NTILE;
#pragma unroll
            for (int j = 0; j < 8; j++) {
                int idx = tid + 256 * j;
                int row = idx >> 5;
                int q   = idx & 31;
                cp_async16(nxt + row * XS + q * 4, xb + row * HW + pn + q * 4);
            }
            cp_commit();
        }

        // ---- Compute: raw fp32 bits as tf32 (HW truncates; bias pre-folded
        //      into W). k outer, 8 independent nt accumulator chains. ----
        float acc[8][4];
#pragma unroll
        for (int nt = 0; nt < 8; nt++) {
            acc[nt][0] = 0.f; acc[nt][1] = 0.f; acc[nt][2] = 0.f; acc[nt][3] = 0.f;
        }
#pragma unroll
        for (int k = 0; k < 8; k++) {
            const float* r0 = cur + (k * 8 + tig)     * XS + nh + g;
            const float* r1 = cur + (k * 8 + 4 + tig) * XS + nh + g;
#pragma unroll
            for (int nt = 0; nt < 8; nt++) {
                uint32_t b0 = __float_as_uint(r0[nt * 8]);
                uint32_t b1 = __float_as_uint(r1[nt * 8]);
                asm volatile(
                    "mma.sync.aligned.m16n8k8.row.col.f32.tf32.tf32.f32 "
                    "{%0,%1,%2,%3}, {%4,%5,%6,%7}, {%8,%9}, {%0,%1,%2,%3};\n"
                    : "+f"(acc[nt][0]), "+f"(acc[nt][1]),
                      "+f"(acc[nt][2]), "+f"(acc[nt][3])
                    : "r"(afr[k][0]), "r"(afr[k][1]),
                      "r"(afr[k][2]), "r"(afr[k][3]),
                      "r"(b0), "r"(b1));
            }
        }

        // ---- Streaming stores ----
#pragma unroll
        for (int nt = 0; nt < 8; nt++) {
            const int c = nh + nt * 8 + 2 * tig;
            float2 v0 = make_float2(acc[nt][0], acc[nt][1]);
            float2 v1 = make_float2(acc[nt][2], acc[nt][3]);
            __stcs(reinterpret_cast<float2*>(ob + (size_t)(m0 + g)     * HW + p0 + c), v0);
            __stcs(reinterpret_cast<float2*>(ob + (size_t)(m0 + 8 + g) * HW + p0 + c), v1);
        }

        cb = (cb + 1 == NBUF) ? 0 : cb + 1;
    }
}

extern "C" void kernel_launch(void* const* d_in, const int* in_sizes, int n_in,
                              void* d_out, int out_size) {
    const float* x     = (const float*)d_in[0];   // [32,64,160,160]
    const float* alpha = (const float*)d_in[1];   // [32,8]
    const float* ke    = (const float*)d_in[2];   // [8,64,64,1,1]
    float*       out   = (float*)d_out;           // [32,64,160,160]

    cudaFuncSetAttribute(lla_conv_kernel,
                         cudaFuncAttributeMaxDynamicSharedMemorySize, SMEM_BYTES);

    dim3 wgrid(BATCH, 4);
    lla_weights_kernel<<<wgrid, 256>>>(alpha, ke);

    dim3 grid(HW / (NTILE * ITERS), BATCH);       // (25, 32)
    lla_conv_kernel<<<grid, 256, SMEM_BYTES>>>(x, out);
}

// round 4
// speedup vs baseline: 1.3699x; 1.1417x over previous
#include <cuda_runtime.h>
#include <cstdint>

// Problem constants
#define BATCH 32
#define NEXP 8
#define CIN 64
#define COUT 64
#define HW 25600            // 160*160
#define NTILE 64            // pixels per tile
#define ITERS 8             // tiles per block
#define XS 72               // padded smem row stride in floats (conflict-free)
#define BUF_FLOATS (CIN * XS)
#define NBUF 3
#define SMEM_BYTES (NBUF * BUF_FLOATS * 4)   // 55296 -> 4 CTAs/SM

// Per-batch mixed weight matrices, TF32-rounded, [B][COUT][CIN]
__device__ float g_W[BATCH * COUT * CIN];

__device__ __forceinline__ uint32_t f2tf32(float f) {
    uint32_t r;
    asm("cvt.rna.tf32.f32 %0, %1;" : "=r"(r) : "f"(f));
    return r;
}

__device__ __forceinline__ void cp_async16(float* dst_smem, const float* src_gmem) {
    uint32_t d = (uint32_t)__cvta_generic_to_shared(dst_smem);
    asm volatile("cp.async.cg.shared.global [%0], [%1], 16;\n" :: "r"(d), "l"(src_gmem));
}
__device__ __forceinline__ void cp_commit() {
    asm volatile("cp.async.commit_group;\n" ::: "memory");
}
template<int N>
__device__ __forceinline__ void cp_wait() {
    asm volatile("cp.async.wait_group %0;\n" :: "n"(N) : "memory");
}

// Kernel 1: W_b[o,i] = (1+3.38e-4) * sum_e alpha[b,e] * ke[e,o,i], tf32-RNA.
// Scale cancels the first-order truncation bias of feeding raw fp32 X bits
// to the tf32 MMA.
__global__ void lla_weights_kernel(const float* __restrict__ alpha,
                                   const float* __restrict__ ke) {
    const int b = blockIdx.x;
    __shared__ float a_s[NEXP];
    if (threadIdx.x < NEXP) a_s[threadIdx.x] = alpha[b * NEXP + threadIdx.x];
    __syncthreads();
    const int i0 = blockIdx.y * 1024 + threadIdx.x;
#pragma unroll 4
    for (int i = i0; i < (blockIdx.y + 1) * 1024; i += 256) {
        float s = 0.f;
#pragma unroll
        for (int e = 0; e < NEXP; e++)
            s = fmaf(a_s[e], ke[e * COUT * CIN + i], s);
        g_W[b * COUT * CIN + i] = __uint_as_float(f2tf32(s * 1.000338f));
    }
}

// Kernel 2: per-batch GEMM via tf32 mma.sync.
// 128-thread CTA (4 warps). Warp w owns M-rows [16w,16w+16), full N=64 tile.
// Depth-2 cp.async pipeline over 8 x 64-pixel tiles; 4 CTAs/SM.
__global__ __launch_bounds__(128, 4)
void lla_conv_kernel(const float* __restrict__ x, float* __restrict__ out) {
    extern __shared__ float smem[];
    float* bufs[NBUF] = { smem, smem + BUF_FLOATS, smem + 2 * BUF_FLOATS };

    const int b    = blockIdx.y;
    const int tid  = threadIdx.x;
    const int lane = tid & 31;
    const int warp = tid >> 5;
    const int g    = lane >> 2;   // 0..7
    const int tig  = lane & 3;    // 0..3
    const int m0   = warp * 16;

    const float* xb = x   + (size_t)b * CIN  * HW;
    float*       ob = out + (size_t)b * COUT * HW;
    const int pbase = blockIdx.x * (NTILE * ITERS);

    // ---- Prefetch tiles 0,1 into buf0,buf1 (16KB each) ----
#pragma unroll
    for (int t = 0; t < 2; t++) {
#pragma unroll
        for (int j = 0; j < 8; j++) {
            int idx = tid + 128 * j;          // 0..1023
            int row = idx >> 4;               // 0..63
            int q   = idx & 15;               // float4 within row
            cp_async16(bufs[t] + row * XS + q * 4,
                       xb + row * HW + pbase + t * NTILE + q * 4);
        }
        cp_commit();
    }

    // ---- Stage W into buf2 region, build A fragments ----
    {
        float* wstage = bufs[2];
        const float* Wg = g_W + b * COUT * CIN;
        for (int idx = tid; idx < COUT * CIN; idx += 128) {
            int o = idx >> 6, i = idx & 63;
            wstage[o * 65 + i] = Wg[idx];
        }
    }
    __syncthreads();

    uint32_t afr[8][4];
#pragma unroll
    for (int k = 0; k < 8; k++) {
        float* wstage = bufs[2];
        int kc = k * 8 + tig;
        afr[k][0] = __float_as_uint(wstage[(m0 + g)     * 65 + kc]);
        afr[k][1] = __float_as_uint(wstage[(m0 + 8 + g) * 65 + kc]);
        afr[k][2] = __float_as_uint(wstage[(m0 + g)     * 65 + kc + 4]);
        afr[k][3] = __float_as_uint(wstage[(m0 + 8 + g) * 65 + kc + 4]);
    }

    int cb = 0;
    for (int it = 0; it < ITERS; it++) {
        float* const cur = bufs[cb];
        const int p0 = pbase + it * NTILE;

        if (it < ITERS - 1) cp_wait<1>(); else cp_wait<0>();
        __syncthreads();   // tile 'it' visible; prior readers of the buffer
                           // about to be refilled are done

        // ---- Prefetch tile it+2 (overlaps with compute) ----
        if (it + 2 < ITERS) {
            float* const nxt = bufs[(cb + 2 >= NBUF) ? cb + 2 - NBUF : cb + 2];
            const int pn = p0 + 2 * NTILE;
#pragma unroll
            for (int j = 0; j < 8; j++) {
                int idx = tid + 128 * j;
                int row = idx >> 4;
                int q   = idx & 15;
                cp_async16(nxt + row * XS + q * 4, xb + row * HW + pn + q * 4);
            }
            cp_commit();
        }

        // ---- Compute: raw fp32 bits as tf32 (bias pre-folded into W).
        //      k outer, 8 independent nt accumulator chains. ----
        float acc[8][4];
#pragma unroll
        for (int nt = 0; nt < 8; nt++) {
            acc[nt][0] = 0.f; acc[nt][1] = 0.f; acc[nt][2] = 0.f; acc[nt][3] = 0.f;
        }
#pragma unroll
        for (int k = 0; k < 8; k++) {
            const float* r0 = cur + (k * 8 + tig)     * XS + g;
            const float* r1 = cur + (k * 8 + 4 + tig) * XS + g;
#pragma unroll
            for (int nt = 0; nt < 8; nt++) {
                uint32_t b0 = __float_as_uint(r0[nt * 8]);
                uint32_t b1 = __float_as_uint(r1[nt * 8]);
                asm volatile(
                    "mma.sync.aligned.m16n8k8.row.col.f32.tf32.tf32.f32 "
                    "{%0,%1,%2,%3}, {%4,%5,%6,%7}, {%8,%9}, {%0,%1,%2,%3};\n"
                    : "+f"(acc[nt][0]), "+f"(acc[nt][1]),
                      "+f"(acc[nt][2]), "+f"(acc[nt][3])
                    : "r"(afr[k][0]), "r"(afr[k][1]),
                      "r"(afr[k][2]), "r"(afr[k][3]),
                      "r"(b0), "r"(b1));
            }
        }

        // ---- Streaming stores ----
#pragma unroll
        for (int nt = 0; nt < 8; nt++) {
            const int c = nt * 8 + 2 * tig;
            float2 v0 = make_float2(acc[nt][0], acc[nt][1]);
            float2 v1 = make_float2(acc[nt][2], acc[nt][3]);
            __stcs(reinterpret_cast<float2*>(ob + (size_t)(m0 + g)     * HW + p0 + c), v0);
            __stcs(reinterpret_cast<float2*>(ob + (size_t)(m0 + 8 + g) * HW + p0 + c), v1);
        }

        cb = (cb + 1 == NBUF) ? 0 : cb + 1;
    }
}

extern "C" void kernel_launch(void* const* d_in, const int* in_sizes, int n_in,
                              void* d_out, int out_size) {
    const float* x     = (const float*)d_in[0];   // [32,64,160,160]
    const float* alpha = (const float*)d_in[1];   // [32,8]
    const float* ke    = (const float*)d_in[2];   // [8,64,64,1,1]
    float*       out   = (float*)d_out;           // [32,64,160,160]

    cudaFuncSetAttribute(lla_conv_kernel,
                         cudaFuncAttributeMaxDynamicSharedMemorySize, SMEM_BYTES);

    dim3 wgrid(BATCH, 4);
    lla_weights_kernel<<<wgrid, 256>>>(alpha, ke);

    dim3 grid(HW / (NTILE * ITERS), BATCH);       // (50, 32)
    lla_conv_kernel<<<grid, 128, SMEM_BYTES>>>(x, out);
}

// round 5
// speedup vs baseline: 1.3737x; 1.0028x over previous
#include <cuda_runtime.h>
#include <cstdint>

// Problem constants
#define BATCH 32
#define NEXP 8
#define CIN 64
#define COUT 64
#define HW 25600            // 160*160
#define NTW 16              // pixels per warp-tile
#define ITERS 8             // tiles per warp
#define XSW 16              // smem row stride in floats (XOR-swizzled, no pad)
#define TILEF (CIN * XSW)   // 1024 floats per stage
#define NBUF 3
#define WARPF (NBUF * TILEF)        // 3072 floats per warp
#define WSM_OFF (8 * WARPF)         // 24576 floats: W-fragment table
#define SMEM_BYTES ((WSM_OFF + 4096) * 4)   // 114688 B -> 2 CTAs/SM

// Per-batch mixed weight matrices, TF32-rounded, [B][COUT][CIN]
__device__ float g_W[BATCH * COUT * CIN];

__device__ __forceinline__ uint32_t f2tf32(float f) {
    uint32_t r;
    asm("cvt.rna.tf32.f32 %0, %1;" : "=r"(r) : "f"(f));
    return r;
}

__device__ __forceinline__ void cp_async16(float* dst_smem, const float* src_gmem) {
    uint32_t d = (uint32_t)__cvta_generic_to_shared(dst_smem);
    asm volatile("cp.async.cg.shared.global [%0], [%1], 16;\n" :: "r"(d), "l"(src_gmem));
}
__device__ __forceinline__ void cp_commit() {
    asm volatile("cp.async.commit_group;\n" ::: "memory");
}
template<int N>
__device__ __forceinline__ void cp_wait() {
    asm volatile("cp.async.wait_group %0;\n" :: "n"(N) : "memory");
}

// Kernel 1: W_b[o,i] = (1+3.38e-4) * sum_e alpha[b,e] * ke[e,o,i], tf32-RNA.
// Scale cancels first-order truncation bias of raw-fp32 X bits into tf32 MMA.
__global__ void lla_weights_kernel(const float* __restrict__ alpha,
                                   const float* __restrict__ ke) {
    const int b = blockIdx.x;
    __shared__ float a_s[NEXP];
    if (threadIdx.x < NEXP) a_s[threadIdx.x] = alpha[b * NEXP + threadIdx.x];
    __syncthreads();
    const int i0 = blockIdx.y * 1024 + threadIdx.x;
#pragma unroll 4
    for (int i = i0; i < (blockIdx.y + 1) * 1024; i += 256) {
        float s = 0.f;
#pragma unroll
        for (int e = 0; e < NEXP; e++)
            s = fmaf(a_s[e], ke[e * COUT * CIN + i], s);
        g_W[b * COUT * CIN + i] = __uint_as_float(f2tf32(s * 1.000338f));
    }
}

// Kernel 2: warp-autonomous tf32-mma pipelines.
// 8 warps/CTA; each warp owns a 16px strip x ITERS tiles, a private 3-stage
// cp.async ring, computes M=64 x N=16 per tile. No CTA barriers in the loop.
__global__ __launch_bounds__(256, 2)
void lla_conv_kernel(const float* __restrict__ x, float* __restrict__ out) {
    extern __shared__ float smem[];

    const int b    = blockIdx.y;
    const int tid  = threadIdx.x;
    const int lane = tid & 31;
    const int warp = tid >> 5;
    const int g    = lane >> 2;     // 0..7
    const int tig  = lane & 3;      // 0..3
    const int sb   = tig >> 1;      // swizzle bit for this thread's B rows

    const float* xb = x   + (size_t)b * CIN  * HW;
    float*       ob = out + (size_t)b * COUT * HW;
    float* const wbuf = smem + warp * WARPF;
    const int pw = (blockIdx.x * 8 + warp) * (NTW * ITERS);   // warp pixel base

    // ---- Prefetch warp-tiles 0,1 into private stages 0,1 ----
    // chunk id = lane + 32j: row = id>>2 (0..63), q = id&3 (16B chunk in row).
    // Swizzled dst chunk: q' = q ^ (2*((row>>1)&1)).
#pragma unroll
    for (int t = 0; t < 2; t++) {
#pragma unroll
        for (int j = 0; j < 8; j++) {
            int id  = lane + 32 * j;
            int row = id >> 2;
            int q   = id & 3;
            int qs  = q ^ (((row >> 1) & 1) << 1);
            cp_async16(wbuf + t * TILEF + row * XSW + qs * 4,
                       xb + row * HW + pw + t * NTW + q * 4);
        }
        cp_commit();
    }

    // ---- Stage W fragment table (shared by all warps; identical layout) ----
    // wsm4[(k*4+m)*32 + lane] = {W[m16+g][k8+tig], W[m16+8+g][k8+tig],
    //                            W[m16+g][k8+tig+4], W[m16+8+g][k8+tig+4]}
    float4* const wsm4 = reinterpret_cast<float4*>(smem + WSM_OFF);
    {
        const float* Wg = g_W + b * COUT * CIN;
        for (int idx = tid; idx < 1024; idx += 256) {
            int l  = idx & 31;
            int km = idx >> 5;
            int m  = km & 3;
            int k  = km >> 2;
            int gg = l >> 2, tt = l & 3;
            int r0 = m * 16 + gg, r1 = r0 + 8;
            int c0 = k * 8 + tt,  c1 = c0 + 4;
            wsm4[idx] = make_float4(Wg[r0 * 64 + c0], Wg[r1 * 64 + c0],
                                    Wg[r0 * 64 + c1], Wg[r1 * 64 + c1]);
        }
    }
    __syncthreads();   // only CTA-wide sync; warps independent afterwards

    for (int it = 0; it < ITERS; it++) {
        float* const cur = wbuf + (it % NBUF) * TILEF;
        const int p0 = pw + it * NTW;

        if (it < ITERS - 1) cp_wait<1>(); else cp_wait<0>();
        __syncwarp();

        // ---- Prefetch tile it+2 into stage (it+2)%NBUF ----
        if (it + 2 < ITERS) {
            float* const nxt = wbuf + ((it + 2) % NBUF) * TILEF;
            const int pn = p0 + 2 * NTW;
#pragma unroll
            for (int j = 0; j < 8; j++) {
                int id  = lane + 32 * j;
                int row = id >> 2;
                int q   = id & 3;
                int qs  = q ^ (((row >> 1) & 1) << 1);
                cp_async16(nxt + row * XSW + qs * 4, xb + row * HW + pn + q * 4);
            }
            cp_commit();
        }

        // ---- Compute: 4 m-subtiles x 2 n-subtiles x 8 k-steps ----
        float acc[4][2][4];
#pragma unroll
        for (int m = 0; m < 4; m++)
#pragma unroll
            for (int n = 0; n < 2; n++) {
                acc[m][n][0] = 0.f; acc[m][n][1] = 0.f;
                acc[m][n][2] = 0.f; acc[m][n][3] = 0.f;
            }
#pragma unroll
        for (int k = 0; k < 8; k++) {
            const int r0 = (k * 8 + tig)     * XSW;
            const int r1 = (k * 8 + 4 + tig) * XSW;
            const int c0 = g       ^ (sb << 3);
            const int c1 = (8 + g) ^ (sb << 3);
            uint32_t b00 = __float_as_uint(cur[r0 + c0]);
            uint32_t b01 = __float_as_uint(cur[r1 + c0]);
            uint32_t b10 = __float_as_uint(cur[r0 + c1]);
            uint32_t b11 = __float_as_uint(cur[r1 + c1]);
#pragma unroll
            for (int m = 0; m < 4; m++) {
                float4 a = wsm4[(k * 4 + m) * 32 + lane];
                uint32_t a0 = __float_as_uint(a.x), a1 = __float_as_uint(a.y);
                uint32_t a2 = __float_as_uint(a.z), a3 = __float_as_uint(a.w);
                asm volatile(
                    "mma.sync.aligned.m16n8k8.row.col.f32.tf32.tf32.f32 "
                    "{%0,%1,%2,%3}, {%4,%5,%6,%7}, {%8,%9}, {%0,%1,%2,%3};\n"
                    : "+f"(acc[m][0][0]), "+f"(acc[m][0][1]),
                      "+f"(acc[m][0][2]), "+f"(acc[m][0][3])
                    : "r"(a0), "r"(a1), "r"(a2), "r"(a3), "r"(b00), "r"(b01));
                asm volatile(
                    "mma.sync.aligned.m16n8k8.row.col.f32.tf32.tf32.f32 "
                    "{%0,%1,%2,%3}, {%4,%5,%6,%7}, {%8,%9}, {%0,%1,%2,%3};\n"
                    : "+f"(acc[m][1][0]), "+f"(acc[m][1][1]),
                      "+f"(acc[m][1][2]), "+f"(acc[m][1][3])
                    : "r"(a0), "r"(a1), "r"(a2), "r"(a3), "r"(b10), "r"(b11));
            }
        }

        // ---- Streaming stores: 32B sectors, fully written ----
#pragma unroll
        for (int m = 0; m < 4; m++)
#pragma unroll
            for (int n = 0; n < 2; n++) {
                const int c = p0 + n * 8 + 2 * tig;
                float2 v0 = make_float2(acc[m][n][0], acc[m][n][1]);
                float2 v1 = make_float2(acc[m][n][2], acc[m][n][3]);
                __stcs(reinterpret_cast<float2*>(ob + (size_t)(m * 16 + g)     * HW + c), v0);
                __stcs(reinterpret_cast<float2*>(ob + (size_t)(m * 16 + 8 + g) * HW + c), v1);
            }
    }
}

extern "C" void kernel_launch(void* const* d_in, const int* in_sizes, int n_in,
                              void* d_out, int out_size) {
    const float* x     = (const float*)d_in[0];   // [32,64,160,160]
    const float* alpha = (const float*)d_in[1];   // [32,8]
    const float* ke    = (const float*)d_in[2];   // [8,64,64,1,1]
    float*       out   = (float*)d_out;           // [32,64,160,160]

    cudaFuncSetAttribute(lla_conv_kernel,
                         cudaFuncAttributeMaxDynamicSharedMemorySize, SMEM_BYTES);

    dim3 wgrid(BATCH, 4);
    lla_weights_kernel<<<wgrid, 256>>>(alpha, ke);

    dim3 grid(HW / (8 * NTW * ITERS), BATCH);     // (25, 32)
    lla_conv_kernel<<<grid, 256, SMEM_BYTES>>>(x, out);
}